// round 3
// baseline (speedup 1.0000x reference)
#include <cuda_runtime.h>
#include <cstdint>

#define EMBED 512
#define NB 8
#define NS 2048
#define M_TOTAL (NB * NS)   // 16384 rows

// attn in (b, h, s, d) contiguous layout == the reference's buggy reshape.
__device__ float g_scratch[NB * NS * EMBED];  // 33.5 MB static device scratch

// ---------------------------------------------------------------------------
// Kernel 1: proj = cos(x + theta); per-token 64-head attention (d_k = 8).
// 4 tokens per 256-thread block; thread = (token-in-block, head).
// Softmax without max-subtraction (scores bounded by sqrt(8)).
// ---------------------------------------------------------------------------
__global__ __launch_bounds__(256) void attn_kernel(
    const float* __restrict__ x, const float* __restrict__ theta)
{
    __shared__ __align__(16) float proj[4 * 64 * 8];  // 4 tokens x 64 heads x 8
    __shared__ float th[8];
    int tid = threadIdx.x;
    if (tid < 8) th[tid] = theta[tid];
    __syncthreads();

    // Load 4 tokens of x (2048 floats, contiguous) and apply cos(x + theta).
    size_t base = (size_t)blockIdx.x * 2048;
    const float4* x4 = (const float4*)(x + base);
#pragma unroll
    for (int i = 0; i < 2; i++) {
        int f = tid + i * 256;
        float4 v = x4[f];
        int d0 = (f & 1) * 4;           // element (4f+c) has wire d = (4f+c)&7
        float* p = proj + f * 4;
        p[0] = __cosf(v.x + th[d0 + 0]);
        p[1] = __cosf(v.y + th[d0 + 1]);
        p[2] = __cosf(v.z + th[d0 + 2]);
        p[3] = __cosf(v.w + th[d0 + 3]);
    }
    __syncthreads();

    int tok = tid >> 6;      // 0..3
    int h   = tid & 63;      // head
    const float4* p4 = (const float4*)(proj + tok * 512);
    float4 A0 = p4[h * 2 + 0];
    float4 A1 = p4[h * 2 + 1];

    float acc0 = 0.f, acc1 = 0.f, acc2 = 0.f, acc3 = 0.f;
    float acc4 = 0.f, acc5 = 0.f, acc6 = 0.f, acc7 = 0.f;
    float l = 0.f;
    // 1/sqrt(8) * log2(e): do exp via exp2
    const float SC = 0.35355339059327373f * 1.4426950408889634f;

#pragma unroll 4
    for (int g = 0; g < 64; g++) {
        float4 q0 = p4[g * 2 + 0];     // broadcast LDS.128 (same addr per warp)
        float4 q1 = p4[g * 2 + 1];
        float dot = A0.x * q0.x + A0.y * q0.y + A0.z * q0.z + A0.w * q0.w
                  + A1.x * q1.x + A1.y * q1.y + A1.z * q1.z + A1.w * q1.w;
        float p = exp2f(dot * SC);     // no max needed: |dot*1/sqrt(8)| <= 2.83
        l += p;
        acc0 += p * q0.x; acc1 += p * q0.y; acc2 += p * q0.z; acc3 += p * q0.w;
        acc4 += p * q1.x; acc5 += p * q1.y; acc6 += p * q1.z; acc7 += p * q1.w;
    }
    float inv = 1.0f / l;

    int token = blockIdx.x * 4 + tok;
    int b = token >> 11;
    int s = token & 2047;
    // (b, h, s, d) layout: offset = b*2^20 + h*2^14 + s*2^3
    size_t off = ((size_t)b << 20) + ((size_t)h << 14) + ((size_t)s << 3);
    float4* o = (float4*)(g_scratch + off);
    o[0] = make_float4(acc0 * inv, acc1 * inv, acc2 * inv, acc3 * inv);
    o[1] = make_float4(acc4 * inv, acc5 * inv, acc6 * inv, acc7 * inv);
}

// ---------------------------------------------------------------------------
// Kernel 2: C[16384,512] = scratch @ W^T + bias, tf32 mma.sync m16n8k8.
// Block tile 128(M) x 128(N), BK=16, 8 warps (2x4), warp tile 64x32.
// Smem padded to 20 floats/row: fragment loads are bank-conflict-free
// ((20*g + t) mod 32 is a permutation over the warp).
// ---------------------------------------------------------------------------
#define BK 16
#define KW 20

__device__ __forceinline__ uint32_t f2tf32(float f) {
    uint32_t r;
    asm("cvt.rna.tf32.f32 %0, %1;" : "=r"(r) : "f"(f));
    return r;
}

__device__ __forceinline__ void mma8(float* c, const uint32_t* a, const uint32_t* b) {
    asm volatile(
        "mma.sync.aligned.m16n8k8.row.col.f32.tf32.tf32.f32 "
        "{%0,%1,%2,%3}, {%4,%5,%6,%7}, {%8,%9}, {%0,%1,%2,%3};\n"
        : "+f"(c[0]), "+f"(c[1]), "+f"(c[2]), "+f"(c[3])
        : "r"(a[0]), "r"(a[1]), "r"(a[2]), "r"(a[3]), "r"(b[0]), "r"(b[1]));
}

__global__ __launch_bounds__(256) void gemm_kernel(
    const float* __restrict__ Wm,     // [512][512] row-major (out, in)
    const float* __restrict__ bias,   // [512]
    float* __restrict__ C)            // [16384][512]
{
    __shared__ __align__(16) uint32_t As[2][128 * KW];
    __shared__ __align__(16) uint32_t Bs[2][128 * KW];
    const float* A = g_scratch;

    int tid  = threadIdx.x;
    int warp = tid >> 5, lane = tid & 31;
    int wm = warp >> 2, wn = warp & 3;     // 2 x 4 warp grid
    int g  = lane >> 2, t = lane & 3;      // groupID, threadID_in_group
    int bm = blockIdx.y, bn = blockIdx.x;

    float c[4][4][4];
#pragma unroll
    for (int mi = 0; mi < 4; mi++)
#pragma unroll
        for (int ni = 0; ni < 4; ni++)
#pragma unroll
            for (int k = 0; k < 4; k++) c[mi][ni][k] = 0.f;

    // Global staging: 128 rows x 16 k-cols per operand per chunk.
    // Thread loads 2 float4 per operand: rows tid/4 and tid/4+64, cols (tid&3)*4.
    int arow0 = bm * 128 + (tid >> 2);
    int brow0 = bn * 128 + (tid >> 2);
    int c4 = tid & 3;
    float4 ra[2], rb[2];

    auto LOAD = [&](int kt) {
        int kc = kt * BK + c4 * 4;
        ra[0] = *(const float4*)&A [(size_t)arow0        * 512 + kc];
        ra[1] = *(const float4*)&A [(size_t)(arow0 + 64) * 512 + kc];
        rb[0] = *(const float4*)&Wm[(size_t)brow0        * 512 + kc];
        rb[1] = *(const float4*)&Wm[(size_t)(brow0 + 64) * 512 + kc];
    };
    auto STORE = [&](int buf) {
#pragma unroll
        for (int i = 0; i < 2; i++) {
            int row = (tid >> 2) + i * 64;
            uint4 ua = make_uint4(f2tf32(ra[i].x), f2tf32(ra[i].y),
                                  f2tf32(ra[i].z), f2tf32(ra[i].w));
            *(uint4*)&As[buf][row * KW + c4 * 4] = ua;
            uint4 ub = make_uint4(f2tf32(rb[i].x), f2tf32(rb[i].y),
                                  f2tf32(rb[i].z), f2tf32(rb[i].w));
            *(uint4*)&Bs[buf][row * KW + c4 * 4] = ub;
        }
    };

    LOAD(0);
    STORE(0);
    __syncthreads();

    for (int kt = 0; kt < 32; kt++) {
        int cur = kt & 1;
        if (kt < 31) LOAD(kt + 1);   // overlap global latency with compute

#pragma unroll
        for (int ks = 0; ks < 2; ks++) {
            int k0 = ks * 8;
            uint32_t af[4][4], bf[4][2];
            const uint32_t* sA = &As[cur][0];
            const uint32_t* sB = &Bs[cur][0];
#pragma unroll
            for (int mi = 0; mi < 4; mi++) {
                int r = wm * 64 + mi * 16 + g;
                af[mi][0] = sA[r       * KW + k0 + t];
                af[mi][1] = sA[(r + 8) * KW + k0 + t];
                af[mi][2] = sA[r       * KW + k0 + t + 4];
                af[mi][3] = sA[(r + 8) * KW + k0 + t + 4];
            }
#pragma unroll
            for (int ni = 0; ni < 4; ni++) {
                int r = wn * 32 + ni * 8 + g;
                bf[ni][0] = sB[r * KW + k0 + t];
                bf[ni][1] = sB[r * KW + k0 + t + 4];
            }
#pragma unroll
            for (int mi = 0; mi < 4; mi++)
#pragma unroll
                for (int ni = 0; ni < 4; ni++)
                    mma8(c[mi][ni], af[mi], bf[ni]);
        }

        if (kt < 31) {
            STORE(1 - cur);
            __syncthreads();
        }
    }

    // Epilogue: C = acc + bias
#pragma unroll
    for (int mi = 0; mi < 4; mi++) {
        int row = bm * 128 + wm * 64 + mi * 16 + g;
#pragma unroll
        for (int ni = 0; ni < 4; ni++) {
            int col = bn * 128 + wn * 32 + ni * 8 + 2 * t;
            float2 bv = *(const float2*)&bias[col];
            *(float2*)&C[(size_t)row * 512 + col] =
                make_float2(c[mi][ni][0] + bv.x, c[mi][ni][1] + bv.y);
            *(float2*)&C[(size_t)(row + 8) * 512 + col] =
                make_float2(c[mi][ni][2] + bv.x, c[mi][ni][3] + bv.y);
        }
    }
}

// ---------------------------------------------------------------------------
extern "C" void kernel_launch(void* const* d_in, const int* in_sizes, int n_in,
                              void* d_out, int out_size)
{
    const float* x     = (const float*)d_in[0];
    const float* theta = (const float*)d_in[1];
    const float* Wm    = (const float*)d_in[2];
    const float* bias  = (const float*)d_in[3];
    float* out = (float*)d_out;

    attn_kernel<<<M_TOTAL / 4, 256>>>(x, theta);

    dim3 grid(4, 128);  // (N tiles, M tiles)
    gemm_kernel<<<grid, 256>>>(Wm, bias, out);
}

// round 4
// speedup vs baseline: 1.0977x; 1.0977x over previous
#include <cuda_runtime.h>
#include <cstdint>

#define EMBED 512
#define NB 8
#define NS 2048
#define M_TOTAL (NB * NS)   // 16384 rows

// attn output in (b, h, s, d) contiguous layout == the reference's buggy
// reshape. Values stored ALREADY tf32-rounded (rna) — GEMM consumes raw bits.
__device__ float g_scratch[NB * NS * EMBED];  // 32 MB static device scratch
__device__ float g_Wtf[EMBED * EMBED];        // tf32-rounded W (1 MB)

// ---------------------------------------------------------------------------
// f32x2 packed-FMA helpers (FFMA2 — only reachable via PTX fma.rn.f32x2)
// ---------------------------------------------------------------------------
typedef unsigned long long u64;

__device__ __forceinline__ u64 ffma2(u64 a, u64 b, u64 c) {
    u64 d;
    asm("fma.rn.f32x2 %0, %1, %2, %3;" : "=l"(d) : "l"(a), "l"(b), "l"(c));
    return d;
}
__device__ __forceinline__ u64 fmul2(u64 a, u64 b) {
    u64 d;
    asm("mul.rn.f32x2 %0, %1, %2;" : "=l"(d) : "l"(a), "l"(b));
    return d;
}
__device__ __forceinline__ u64 pack2(float lo, float hi) {
    u64 d;
    asm("mov.b64 %0, {%1, %2};" : "=l"(d) : "f"(lo), "f"(hi));
    return d;
}
__device__ __forceinline__ float2 unpack2(u64 v) {
    float lo, hi;
    asm("mov.b64 {%0, %1}, %2;" : "=f"(lo), "=f"(hi) : "l"(v));
    return make_float2(lo, hi);
}
__device__ __forceinline__ float ex2f(float a) {
    float r;
    asm("ex2.approx.ftz.f32 %0, %1;" : "=f"(r) : "f"(a));
    return r;
}
__device__ __forceinline__ uint32_t f2tf32(float f) {
    uint32_t r;
    asm("cvt.rna.tf32.f32 %0, %1;" : "=r"(r) : "f"(f));
    return r;
}

// ---------------------------------------------------------------------------
// Kernel 0: round W to tf32 once per launch (1 MB, ~2us)
// ---------------------------------------------------------------------------
__global__ __launch_bounds__(256) void roundW_kernel(const float* __restrict__ W)
{
    int i = blockIdx.x * 256 + threadIdx.x;   // 65536 float4s
    float4 v = ((const float4*)W)[i];
    uint4 u = make_uint4(f2tf32(v.x), f2tf32(v.y), f2tf32(v.z), f2tf32(v.w));
    ((uint4*)g_Wtf)[i] = u;
}

// ---------------------------------------------------------------------------
// Kernel 1: proj = cos(x + theta); per-token 64-head attention (d_k = 8).
// 4 tokens per 256-thread block; thread = (token-in-block, head).
// Softmax without max-subtraction (|score/sqrt(8)| <= 2.83).
// Inner loop uses packed f32x2 FMA to halve fma-pipe occupancy.
// Output written tf32-rounded for the downstream GEMM.
// ---------------------------------------------------------------------------
__global__ __launch_bounds__(256) void attn_kernel(
    const float* __restrict__ x, const float* __restrict__ theta)
{
    __shared__ __align__(16) float proj[4 * 64 * 8];  // 4 tokens x 64 heads x 8
    __shared__ float th[8];
    int tid = threadIdx.x;
    if (tid < 8) th[tid] = theta[tid];
    __syncthreads();

    // Load 4 tokens of x (2048 floats) and apply cos(x + theta).
    size_t base = (size_t)blockIdx.x * 2048;
    const float4* x4 = (const float4*)(x + base);
#pragma unroll
    for (int i = 0; i < 2; i++) {
        int f = tid + i * 256;
        float4 v = x4[f];
        int d0 = (f & 1) * 4;           // element (4f+c) has wire d = (4f+c)&7
        float* p = proj + f * 4;
        p[0] = __cosf(v.x + th[d0 + 0]);
        p[1] = __cosf(v.y + th[d0 + 1]);
        p[2] = __cosf(v.z + th[d0 + 2]);
        p[3] = __cosf(v.w + th[d0 + 3]);
    }
    __syncthreads();

    int tok = tid >> 6;      // 0..3
    int h   = tid & 63;      // head
    const ulonglong2* pq = (const ulonglong2*)(proj + tok * 512);

    // This head's 8 proj values as 4 packed f32x2.
    ulonglong2 Aa = pq[h * 2 + 0];
    ulonglong2 Ab = pq[h * 2 + 1];
    u64 AP0 = Aa.x, AP1 = Aa.y, AP2 = Ab.x, AP3 = Ab.y;

    u64 ACC0 = 0, ACC1 = 0, ACC2 = 0, ACC3 = 0;
    float l = 0.f;
    // 1/sqrt(8) * log2(e)
    const float SC = 0.35355339059327373f * 1.4426950408889634f;

#pragma unroll 4
    for (int g = 0; g < 64; g++) {
        ulonglong2 qa = pq[g * 2 + 0];   // LDS.128 broadcast within warp
        ulonglong2 qb = pq[g * 2 + 1];
        u64 dp = ffma2(AP0, qa.x,
                 ffma2(AP1, qa.y,
                 ffma2(AP2, qb.x,
                 fmul2(AP3, qb.y))));
        float2 dd = unpack2(dp);
        float p = ex2f((dd.x + dd.y) * SC);   // no max needed
        l += p;
        u64 pp = pack2(p, p);
        ACC0 = ffma2(pp, qa.x, ACC0);
        ACC1 = ffma2(pp, qa.y, ACC1);
        ACC2 = ffma2(pp, qb.x, ACC2);
        ACC3 = ffma2(pp, qb.y, ACC3);
    }
    float inv = 1.0f / l;

    float2 a0 = unpack2(ACC0), a1 = unpack2(ACC1);
    float2 a2 = unpack2(ACC2), a3 = unpack2(ACC3);

    int token = blockIdx.x * 4 + tok;
    int b = token >> 11;
    int s = token & 2047;
    // (b, h, s, d) layout: offset = b*2^20 + h*2^14 + s*2^3
    size_t off = ((size_t)b << 20) + ((size_t)h << 14) + ((size_t)s << 3);
    uint4* o = (uint4*)(g_scratch + off);
    o[0] = make_uint4(f2tf32(a0.x * inv), f2tf32(a0.y * inv),
                      f2tf32(a1.x * inv), f2tf32(a1.y * inv));
    o[1] = make_uint4(f2tf32(a2.x * inv), f2tf32(a2.y * inv),
                      f2tf32(a3.x * inv), f2tf32(a3.y * inv));
}

// ---------------------------------------------------------------------------
// Kernel 2: C[16384,512] = scratch @ W^T + bias, tf32 mma.sync m16n8k8.
// Block tile 128x128, BK=16, 8 warps (2x4), warp tile 64x32.
// 3-stage cp.async pipeline; XOR-swizzled smem (16B chunk ^ ((row>>1)&3)):
//   - fragment LDS.32 bank = 16(g&1) + 4(c ^ ((g>>1)&3)) + t  -> permutation,
//     conflict-free
//   - 3 stages x 2 operands x 8KB = 48KB static smem exactly.
// Inputs are pre-rounded to tf32, so no cvt in the hot loop.
// ---------------------------------------------------------------------------
#define STAGES 3
#define STAGE_WORDS 2048   // 128 rows * 16 words

__device__ __forceinline__ void cp_async16(uint32_t dst, const void* src) {
    asm volatile("cp.async.cg.shared.global [%0], [%1], 16;"
                 :: "r"(dst), "l"(src));
}
#define CP_COMMIT() asm volatile("cp.async.commit_group;")
#define CP_WAIT(n)  asm volatile("cp.async.wait_group %0;" :: "n"(n))

__device__ __forceinline__ uint32_t lds_w(const uint32_t* s, int row, int col) {
    int idx = row * 16 + ((((col >> 2) ^ ((row >> 1) & 3)) << 2) | (col & 3));
    return s[idx];
}

__device__ __forceinline__ void mma8(float* c, const uint32_t* a, const uint32_t* b) {
    asm volatile(
        "mma.sync.aligned.m16n8k8.row.col.f32.tf32.tf32.f32 "
        "{%0,%1,%2,%3}, {%4,%5,%6,%7}, {%8,%9}, {%0,%1,%2,%3};\n"
        : "+f"(c[0]), "+f"(c[1]), "+f"(c[2]), "+f"(c[3])
        : "r"(a[0]), "r"(a[1]), "r"(a[2]), "r"(a[3]), "r"(b[0]), "r"(b[1]));
}

__global__ __launch_bounds__(256) void gemm_kernel(
    const float* __restrict__ bias,   // [512]
    float* __restrict__ C)            // [16384][512]
{
    __shared__ __align__(16) uint32_t As[STAGES][STAGE_WORDS];
    __shared__ __align__(16) uint32_t Bs[STAGES][STAGE_WORDS];
    const float* A = g_scratch;
    const float* B = g_Wtf;

    int tid  = threadIdx.x;
    int warp = tid >> 5, lane = tid & 31;
    int wm = warp >> 2, wn = warp & 3;     // 2 x 4 warp grid
    int g  = lane >> 2, t = lane & 3;      // groupID, threadID_in_group
    int bm = blockIdx.y, bn = blockIdx.x;

    float c[4][4][4];
#pragma unroll
    for (int mi = 0; mi < 4; mi++)
#pragma unroll
        for (int ni = 0; ni < 4; ni++)
#pragma unroll
            for (int k = 0; k < 4; k++) c[mi][ni][k] = 0.f;

    // Staging: thread handles rows (tid>>2, +64), 16B chunk (tid&3), both ops.
    int sr = tid >> 2, sc = tid & 3;
    uint32_t sAb = (uint32_t)__cvta_generic_to_shared(&As[0][0]);
    uint32_t sBb = (uint32_t)__cvta_generic_to_shared(&Bs[0][0]);

    auto issue = [&](int kt, int s) {
        int kc = kt * 16 + sc * 4;
#pragma unroll
        for (int i = 0; i < 2; i++) {
            int lr = sr + i * 64;
            uint32_t off = (uint32_t)(lr * 16 + ((sc ^ ((lr >> 1) & 3)) << 2)) * 4
                         + (uint32_t)s * (STAGE_WORDS * 4);
            cp_async16(sAb + off, &A[(size_t)(bm * 128 + lr) * 512 + kc]);
            cp_async16(sBb + off, &B[(size_t)(bn * 128 + lr) * 512 + kc]);
        }
        CP_COMMIT();
    };

    issue(0, 0);
    issue(1, 1);

    for (int kt = 0; kt < 32; kt++) {
        int s = kt % 3;
        CP_WAIT(1);
        __syncthreads();
        if (kt + 2 < 32) issue(kt + 2, (kt + 2) % 3);

        const uint32_t* sA = &As[s][0];
        const uint32_t* sB = &Bs[s][0];
#pragma unroll
        for (int ks = 0; ks < 2; ks++) {
            int k0 = ks * 8;
            uint32_t af[4][4], bf[4][2];
#pragma unroll
            for (int mi = 0; mi < 4; mi++) {
                int r = wm * 64 + mi * 16 + g;
                af[mi][0] = lds_w(sA, r,     k0 + t);
                af[mi][1] = lds_w(sA, r + 8, k0 + t);
                af[mi][2] = lds_w(sA, r,     k0 + t + 4);
                af[mi][3] = lds_w(sA, r + 8, k0 + t + 4);
            }
#pragma unroll
            for (int ni = 0; ni < 4; ni++) {
                int r = wn * 32 + ni * 8 + g;
                bf[ni][0] = lds_w(sB, r, k0 + t);
                bf[ni][1] = lds_w(sB, r, k0 + t + 4);
            }
#pragma unroll
            for (int mi = 0; mi < 4; mi++)
#pragma unroll
                for (int ni = 0; ni < 4; ni++)
                    mma8(c[mi][ni], af[mi], bf[ni]);
        }
    }

    // Epilogue: C = acc + bias
#pragma unroll
    for (int mi = 0; mi < 4; mi++) {
        int row = bm * 128 + wm * 64 + mi * 16 + g;
#pragma unroll
        for (int ni = 0; ni < 4; ni++) {
            int col = bn * 128 + wn * 32 + ni * 8 + 2 * t;
            float2 bv = *(const float2*)&bias[col];
            *(float2*)&C[(size_t)row * 512 + col] =
                make_float2(c[mi][ni][0] + bv.x, c[mi][ni][1] + bv.y);
            *(float2*)&C[(size_t)(row + 8) * 512 + col] =
                make_float2(c[mi][ni][2] + bv.x, c[mi][ni][3] + bv.y);
        }
    }
}

// ---------------------------------------------------------------------------
extern "C" void kernel_launch(void* const* d_in, const int* in_sizes, int n_in,
                              void* d_out, int out_size)
{
    const float* x     = (const float*)d_in[0];
    const float* theta = (const float*)d_in[1];
    const float* Wm    = (const float*)d_in[2];
    const float* bias  = (const float*)d_in[3];
    float* out = (float*)d_out;

    roundW_kernel<<<256, 256>>>(Wm);
    attn_kernel<<<M_TOTAL / 4, 256>>>(x, theta);

    dim3 grid(4, 128);  // (N tiles, M tiles)
    gemm_kernel<<<grid, 256>>>(bias, out);
}

// round 6
// speedup vs baseline: 1.2327x; 1.1229x over previous
#include <cuda_runtime.h>
#include <cstdint>

#define EMBED 512
#define NB 8
#define NS 2048
#define M_TOTAL (NB * NS)   // 16384 rows

// attn output in (b, h, s, d) contiguous layout == the reference's buggy
// reshape. Values stored ALREADY tf32-rounded (rna) — GEMM consumes raw bits.
__device__ float g_scratch[M_TOTAL * EMBED];  // 32 MB static device scratch
__device__ float g_Wtf[EMBED * EMBED];        // tf32-rounded W (1 MB)

typedef unsigned long long u64;

// ---------------------------------------------------------------------------
// helpers
// ---------------------------------------------------------------------------
__device__ __forceinline__ u64 ffma2(u64 a, u64 b, u64 c) {
    u64 d;
    asm("fma.rn.f32x2 %0, %1, %2, %3;" : "=l"(d) : "l"(a), "l"(b), "l"(c));
    return d;
}
__device__ __forceinline__ u64 fmul2(u64 a, u64 b) {
    u64 d;
    asm("mul.rn.f32x2 %0, %1, %2;" : "=l"(d) : "l"(a), "l"(b));
    return d;
}
__device__ __forceinline__ u64 pack2(float lo, float hi) {
    u64 d;
    asm("mov.b64 %0, {%1, %2};" : "=l"(d) : "f"(lo), "f"(hi));
    return d;
}
__device__ __forceinline__ float2 unpack2(u64 v) {
    float lo, hi;
    asm("mov.b64 {%0, %1}, %2;" : "=f"(lo), "=f"(hi) : "l"(v));
    return make_float2(lo, hi);
}
__device__ __forceinline__ float ex2f(float a) {
    float r;
    asm("ex2.approx.ftz.f32 %0, %1;" : "=f"(r) : "f"(a));
    return r;
}
__device__ __forceinline__ uint32_t f2tf32(float f) {
    uint32_t r;
    asm("cvt.rna.tf32.f32 %0, %1;" : "=r"(r) : "f"(f));
    return r;
}

__device__ __forceinline__ void cp_async16(uint32_t dst, const void* src) {
    asm volatile("cp.async.cg.shared.global [%0], [%1], 16;" :: "r"(dst), "l"(src));
}
#define CP_COMMIT() asm volatile("cp.async.commit_group;")
#define CP_WAIT(n)  asm volatile("cp.async.wait_group %0;" :: "n"(n))

__device__ __forceinline__ void mma8(float* c, const uint32_t* a, const uint32_t* b) {
    asm volatile(
        "mma.sync.aligned.m16n8k8.row.col.f32.tf32.tf32.f32 "
        "{%0,%1,%2,%3}, {%4,%5,%6,%7}, {%8,%9}, {%0,%1,%2,%3};\n"
        : "+f"(c[0]), "+f"(c[1]), "+f"(c[2]), "+f"(c[3])
        : "r"(a[0]), "r"(a[1]), "r"(a[2]), "r"(a[3]), "r"(b[0]), "r"(b[1]));
}

// ---------------------------------------------------------------------------
// Kernel 1: proj = cos(x + theta); per-token 64-head attention (d_k = 8).
// Softmax without max-subtraction; packed f32x2 FMA inner loop.
// Blocks 0..255 additionally round W to tf32 (replaces separate kernel).
// Output tf32-rounded in (b, h, s, d) layout.
// ---------------------------------------------------------------------------
__global__ __launch_bounds__(256) void attn_kernel(
    const float* __restrict__ x, const float* __restrict__ theta,
    const float* __restrict__ W)
{
    __shared__ __align__(16) float proj[4 * 64 * 8];
    __shared__ float th[8];
    int tid = threadIdx.x;

    // Fold W tf32-rounding into the first 256 blocks (65536 float4s total).
    if (blockIdx.x < 256) {
        int i = blockIdx.x * 256 + tid;
        float4 v = ((const float4*)W)[i];
        uint4 u = make_uint4(f2tf32(v.x), f2tf32(v.y), f2tf32(v.z), f2tf32(v.w));
        ((uint4*)g_Wtf)[i] = u;
    }

    if (tid < 8) th[tid] = theta[tid];
    __syncthreads();

    size_t base = (size_t)blockIdx.x * 2048;
    const float4* x4 = (const float4*)(x + base);
#pragma unroll
    for (int i = 0; i < 2; i++) {
        int f = tid + i * 256;
        float4 v = x4[f];
        int d0 = (f & 1) * 4;
        float* p = proj + f * 4;
        p[0] = __cosf(v.x + th[d0 + 0]);
        p[1] = __cosf(v.y + th[d0 + 1]);
        p[2] = __cosf(v.z + th[d0 + 2]);
        p[3] = __cosf(v.w + th[d0 + 3]);
    }
    __syncthreads();

    int tok = tid >> 6;
    int h   = tid & 63;
    const ulonglong2* pq = (const ulonglong2*)(proj + tok * 512);

    ulonglong2 Aa = pq[h * 2 + 0];
    ulonglong2 Ab = pq[h * 2 + 1];
    // Pre-scale by 1/sqrt(8)*log2(e) so the per-iter FMUL disappears.
    const float SC = 0.35355339059327373f * 1.4426950408889634f;
    u64 scp = pack2(SC, SC);
    u64 AP0 = fmul2(Aa.x, scp), AP1 = fmul2(Aa.y, scp);
    u64 AP2 = fmul2(Ab.x, scp), AP3 = fmul2(Ab.y, scp);

    u64 ACC0 = 0, ACC1 = 0, ACC2 = 0, ACC3 = 0;
    float l = 0.f;

#pragma unroll 4
    for (int g = 0; g < 64; g++) {
        ulonglong2 qa = pq[g * 2 + 0];   // LDS.128 broadcast within warp
        ulonglong2 qb = pq[g * 2 + 1];
        u64 dp = ffma2(AP0, qa.x,
                 ffma2(AP1, qa.y,
                 ffma2(AP2, qb.x,
                 fmul2(AP3, qb.y))));
        float2 dd = unpack2(dp);
        float p = ex2f(dd.x + dd.y);     // no max needed: |arg| <= 4.1
        l += p;
        u64 pp = pack2(p, p);
        ACC0 = ffma2(pp, qa.x, ACC0);
        ACC1 = ffma2(pp, qa.y, ACC1);
        ACC2 = ffma2(pp, qb.x, ACC2);
        ACC3 = ffma2(pp, qb.y, ACC3);
    }
    float inv = 1.0f / l;

    float2 a0 = unpack2(ACC0), a1 = unpack2(ACC1);
    float2 a2 = unpack2(ACC2), a3 = unpack2(ACC3);

    int token = blockIdx.x * 4 + tok;
    int b = token >> 11;
    int s = token & 2047;
    size_t off = ((size_t)b << 20) + ((size_t)h << 14) + ((size_t)s << 3);
    uint4* o = (uint4*)(g_scratch + off);
    o[0] = make_uint4(f2tf32(a0.x * inv), f2tf32(a0.y * inv),
                      f2tf32(a1.x * inv), f2tf32(a1.y * inv));
    o[1] = make_uint4(f2tf32(a2.x * inv), f2tf32(a2.y * inv),
                      f2tf32(a3.x * inv), f2tf32(a3.y * inv));
}

// ---------------------------------------------------------------------------
// Kernel 2: C[16384,512] = scratch @ W^T + bias, tf32 mma.sync m16n8k8.
// Block tile 128x128, BK=32, 8 warps (2x4), warp tile 64x32.
// 3-stage cp.async pipeline (36KB/stage, dynamic smem).
// Padded rows (36 words): conflict-free stores AND fragment loads, with
// every fragment address = base + compile-time immediate (no in-loop ALU).
// Inputs pre-rounded to tf32: no cvt anywhere in the hot loop.
// ---------------------------------------------------------------------------
#define ROWW 36                    // words per padded 32-word row
#define STAGE_WORDS (256 * ROWW)   // A(128 rows) + B(128 rows) = 9216 words
#define NSTAGE 3
#define GEMM_SMEM (NSTAGE * STAGE_WORDS * 4)   // 110592 bytes

__global__ __launch_bounds__(256) void gemm_kernel(
    const float* __restrict__ bias,   // [512]
    float* __restrict__ C)            // [16384][512]
{
    extern __shared__ __align__(16) uint32_t sm[];
    const float* A = g_scratch;
    const float* B = g_Wtf;

    int tid  = threadIdx.x;
    int warp = tid >> 5, lane = tid & 31;
    int wm = warp >> 2, wn = warp & 3;     // 2 x 4 warp grid
    int g  = lane >> 2, t = lane & 3;      // groupID, threadID_in_group
    int bm = blockIdx.y, bn = blockIdx.x;

    float c[4][4][4];
#pragma unroll
    for (int mi = 0; mi < 4; mi++)
#pragma unroll
        for (int ni = 0; ni < 4; ni++)
#pragma unroll
            for (int k = 0; k < 4; k++) c[mi][ni][k] = 0.f;

    // Staging: per stage, 2048 16B-chunks (A:1024, B:1024), 8 per thread.
    // chunk u: row = u>>3, c16 = u&7; smem word = row*ROWW + c16*4 (A),
    // +128*ROWW for B. Store phases are conflict-free (bank = 4*c16 + 4*row).
    uint32_t smb = (uint32_t)__cvta_generic_to_shared(sm);
    const float* gA = A + (size_t)(bm * 128) * 512;
    const float* gB = B + (size_t)(bn * 128) * 512;

    auto produce = [&](int kt, int s) {
        uint32_t st = smb + (uint32_t)s * (STAGE_WORDS * 4);
        int kc = kt * 32;
#pragma unroll
        for (int i = 0; i < 4; i++) {
            int u = i * 256 + tid;
            int row = u >> 3, c16 = u & 7;
            cp_async16(st + (row * ROWW + c16 * 4) * 4,
                       gA + (size_t)row * 512 + kc + c16 * 4);
            cp_async16(st + ((128 + row) * ROWW + c16 * 4) * 4,
                       gB + (size_t)row * 512 + kc + c16 * 4);
        }
        CP_COMMIT();
    };

    produce(0, 0);
    produce(1, 1);

    // Per-thread fragment bases (word indices); all hot-loop offsets immediate.
    const uint32_t* aBase0 = sm + (wm * 64 + g) * ROWW + t;
    const uint32_t* bBase0 = sm + (128 + wn * 32 + g) * ROWW + t;

    for (int kt = 0; kt < 16; kt++) {
        int s = kt % 3;
        CP_WAIT(1);
        __syncthreads();
        if (kt + 2 < 16) produce(kt + 2, (kt + 2) % 3);

        const uint32_t* aB = aBase0 + s * STAGE_WORDS;
        const uint32_t* bB = bBase0 + s * STAGE_WORDS;
#pragma unroll
        for (int ks = 0; ks < 4; ks++) {
            uint32_t af[4][4], bf[4][2];
#pragma unroll
            for (int mi = 0; mi < 4; mi++) {
                af[mi][0] = aB[mi * 16 * ROWW + ks * 8];
                af[mi][1] = aB[(mi * 16 + 8) * ROWW + ks * 8];
                af[mi][2] = aB[mi * 16 * ROWW + ks * 8 + 4];
                af[mi][3] = aB[(mi * 16 + 8) * ROWW + ks * 8 + 4];
            }
#pragma unroll
            for (int ni = 0; ni < 4; ni++) {
                bf[ni][0] = bB[ni * 8 * ROWW + ks * 8];
                bf[ni][1] = bB[ni * 8 * ROWW + ks * 8 + 4];
            }
#pragma unroll
            for (int mi = 0; mi < 4; mi++)
#pragma unroll
                for (int ni = 0; ni < 4; ni++)
                    mma8(c[mi][ni], af[mi], bf[ni]);
        }
    }

    // Epilogue: C = acc + bias
#pragma unroll
    for (int mi = 0; mi < 4; mi++) {
        int row = bm * 128 + wm * 64 + mi * 16 + g;
#pragma unroll
        for (int ni = 0; ni < 4; ni++) {
            int col = bn * 128 + wn * 32 + ni * 8 + 2 * t;
            float2 bv = *(const float2*)&bias[col];
            *(float2*)&C[(size_t)row * 512 + col] =
                make_float2(c[mi][ni][0] + bv.x, c[mi][ni][1] + bv.y);
            *(float2*)&C[(size_t)(row + 8) * 512 + col] =
                make_float2(c[mi][ni][2] + bv.x, c[mi][ni][3] + bv.y);
        }
    }
}

// ---------------------------------------------------------------------------
extern "C" void kernel_launch(void* const* d_in, const int* in_sizes, int n_in,
                              void* d_out, int out_size)
{
    const float* x     = (const float*)d_in[0];
    const float* theta = (const float*)d_in[1];
    const float* Wm    = (const float*)d_in[2];
    const float* bias  = (const float*)d_in[3];
    float* out = (float*)d_out;

    cudaFuncSetAttribute(gemm_kernel,
                         cudaFuncAttributeMaxDynamicSharedMemorySize, GEMM_SMEM);

    attn_kernel<<<M_TOTAL / 4, 256>>>(x, theta, Wm);

    dim3 grid(4, 128);  // (N tiles, M tiles)
    gemm_kernel<<<grid, 256, GEMM_SMEM>>>(bias, out);
}

// round 7
// speedup vs baseline: 1.6460x; 1.3353x over previous
#include <cuda_runtime.h>
#include <cuda_fp16.h>
#include <cstdint>

#define EMBED 512
#define NB 8
#define NS 2048
#define M_TOTAL (NB * NS)   // 16384 rows

// attn output in (b, h, s, d) contiguous layout == the reference's buggy
// reshape. Stored as fp16 (10-bit mantissa == tf32) for the fp16 GEMM.
__device__ __half g_scratch[M_TOTAL * EMBED];  // 16 MB static device scratch
__device__ __half g_Whf[EMBED * EMBED];        // fp16-rounded W (0.5 MB)

typedef unsigned long long u64;

// ---------------------------------------------------------------------------
// helpers
// ---------------------------------------------------------------------------
__device__ __forceinline__ u64 ffma2(u64 a, u64 b, u64 c) {
    u64 d;
    asm("fma.rn.f32x2 %0, %1, %2, %3;" : "=l"(d) : "l"(a), "l"(b), "l"(c));
    return d;
}
__device__ __forceinline__ u64 fmul2(u64 a, u64 b) {
    u64 d;
    asm("mul.rn.f32x2 %0, %1, %2;" : "=l"(d) : "l"(a), "l"(b));
    return d;
}
__device__ __forceinline__ u64 pack2(float lo, float hi) {
    u64 d;
    asm("mov.b64 %0, {%1, %2};" : "=l"(d) : "f"(lo), "f"(hi));
    return d;
}
__device__ __forceinline__ float2 unpack2(u64 v) {
    float lo, hi;
    asm("mov.b64 {%0, %1}, %2;" : "=f"(lo), "=f"(hi) : "l"(v));
    return make_float2(lo, hi);
}
__device__ __forceinline__ float ex2f(float a) {
    float r;
    asm("ex2.approx.ftz.f32 %0, %1;" : "=f"(r) : "f"(a));
    return r;
}

__device__ __forceinline__ void cp_async16(uint32_t dst, const void* src) {
    asm volatile("cp.async.cg.shared.global [%0], [%1], 16;" :: "r"(dst), "l"(src));
}
#define CP_COMMIT() asm volatile("cp.async.commit_group;")
#define CP_WAIT(n)  asm volatile("cp.async.wait_group %0;" :: "n"(n))

__device__ __forceinline__ void ldsm4(uint32_t* r, uint32_t addr) {
    asm volatile("ldmatrix.sync.aligned.m8n8.x4.shared.b16 {%0,%1,%2,%3}, [%4];"
                 : "=r"(r[0]), "=r"(r[1]), "=r"(r[2]), "=r"(r[3]) : "r"(addr));
}

__device__ __forceinline__ void mma16(float* c, const uint32_t* a, const uint32_t* b) {
    asm volatile(
        "mma.sync.aligned.m16n8k16.row.col.f32.f16.f16.f32 "
        "{%0,%1,%2,%3}, {%4,%5,%6,%7}, {%8,%9}, {%0,%1,%2,%3};\n"
        : "+f"(c[0]), "+f"(c[1]), "+f"(c[2]), "+f"(c[3])
        : "r"(a[0]), "r"(a[1]), "r"(a[2]), "r"(a[3]), "r"(b[0]), "r"(b[1]));
}

// ---------------------------------------------------------------------------
// Kernel 1: proj = cos(x + theta); per-token 64-head attention (d_k = 8).
// Softmax without max-subtraction; packed f32x2 FMA inner loop.
// Blocks 0..255 additionally round W to fp16. Output as fp16 in
// (b, h, s, d) layout.
// ---------------------------------------------------------------------------
__global__ __launch_bounds__(256) void attn_kernel(
    const float* __restrict__ x, const float* __restrict__ theta,
    const float* __restrict__ W)
{
    __shared__ __align__(16) float proj[4 * 64 * 8];
    __shared__ float th[8];
    int tid = threadIdx.x;

    // Fold W fp16-rounding into the first 256 blocks (65536 float4s total).
    if (blockIdx.x < 256) {
        int i = blockIdx.x * 256 + tid;
        float4 v = ((const float4*)W)[i];
        __half2 h0 = __floats2half2_rn(v.x, v.y);
        __half2 h1 = __floats2half2_rn(v.z, v.w);
        uint2 u;
        u.x = *(uint32_t*)&h0;
        u.y = *(uint32_t*)&h1;
        ((uint2*)g_Whf)[i] = u;
    }

    if (tid < 8) th[tid] = theta[tid];
    __syncthreads();

    size_t base = (size_t)blockIdx.x * 2048;
    const float4* x4 = (const float4*)(x + base);
#pragma unroll
    for (int i = 0; i < 2; i++) {
        int f = tid + i * 256;
        float4 v = x4[f];
        int d0 = (f & 1) * 4;
        float* p = proj + f * 4;
        p[0] = __cosf(v.x + th[d0 + 0]);
        p[1] = __cosf(v.y + th[d0 + 1]);
        p[2] = __cosf(v.z + th[d0 + 2]);
        p[3] = __cosf(v.w + th[d0 + 3]);
    }
    __syncthreads();

    int tok = tid >> 6;
    int h   = tid & 63;
    const ulonglong2* pq = (const ulonglong2*)(proj + tok * 512);

    ulonglong2 Aa = pq[h * 2 + 0];
    ulonglong2 Ab = pq[h * 2 + 1];
    // Pre-scale by 1/sqrt(8)*log2(e) so the per-iter FMUL disappears.
    const float SC = 0.35355339059327373f * 1.4426950408889634f;
    u64 scp = pack2(SC, SC);
    u64 AP0 = fmul2(Aa.x, scp), AP1 = fmul2(Aa.y, scp);
    u64 AP2 = fmul2(Ab.x, scp), AP3 = fmul2(Ab.y, scp);

    u64 ACC0 = 0, ACC1 = 0, ACC2 = 0, ACC3 = 0;
    float l = 0.f;

#pragma unroll 4
    for (int g = 0; g < 64; g++) {
        ulonglong2 qa = pq[g * 2 + 0];   // LDS.128 broadcast within warp
        ulonglong2 qb = pq[g * 2 + 1];
        u64 dp = ffma2(AP0, qa.x,
                 ffma2(AP1, qa.y,
                 ffma2(AP2, qb.x,
                 fmul2(AP3, qb.y))));
        float2 dd = unpack2(dp);
        float p = ex2f(dd.x + dd.y);     // no max needed: |arg| <= 4.1
        l += p;
        u64 pp = pack2(p, p);
        ACC0 = ffma2(pp, qa.x, ACC0);
        ACC1 = ffma2(pp, qa.y, ACC1);
        ACC2 = ffma2(pp, qb.x, ACC2);
        ACC3 = ffma2(pp, qb.y, ACC3);
    }
    float inv = 1.0f / l;

    float2 a0 = unpack2(ACC0), a1 = unpack2(ACC1);
    float2 a2 = unpack2(ACC2), a3 = unpack2(ACC3);

    int token = blockIdx.x * 4 + tok;
    int b = token >> 11;
    int s = token & 2047;
    size_t off = ((size_t)b << 20) + ((size_t)h << 14) + ((size_t)s << 3);
    __half2 h0 = __floats2half2_rn(a0.x * inv, a0.y * inv);
    __half2 h1 = __floats2half2_rn(a1.x * inv, a1.y * inv);
    __half2 h2 = __floats2half2_rn(a2.x * inv, a2.y * inv);
    __half2 h3 = __floats2half2_rn(a3.x * inv, a3.y * inv);
    uint4 uo;
    uo.x = *(uint32_t*)&h0; uo.y = *(uint32_t*)&h1;
    uo.z = *(uint32_t*)&h2; uo.w = *(uint32_t*)&h3;
    *(uint4*)(g_scratch + off) = uo;
}

// ---------------------------------------------------------------------------
// Kernel 2: C[16384,512] = scratch @ W^T + bias, fp16 mma m16n8k16 (f32 acc).
// Block tile 128x128, BK=32, 8 warps (2x4), warp tile 64x32.
// 4-stage cp.async pipeline (20KB/stage, dynamic smem, 2 CTA/SM).
// fp16 rows padded to 20 words (32 halfs + 8 pad): ldmatrix phases are
// conflict-free ({20r mod 32} + 4-word spans tile all 32 banks).
// Fragments fed by ldmatrix.x4: 12 LDSM + 32 HMMA per warp per kt.
// ---------------------------------------------------------------------------
#define ROWW 20                    // words per padded 16-word (32-half) row
#define STAGE_WORDS (256 * ROWW)   // A(128 rows) + B(128 rows) = 5120 words
#define NSTAGE 4
#define GEMM_SMEM (NSTAGE * STAGE_WORDS * 4)   // 81920 bytes

__global__ __launch_bounds__(256) void gemm_kernel(
    const float* __restrict__ bias,   // [512]
    float* __restrict__ C)            // [16384][512]
{
    extern __shared__ __align__(16) uint32_t sm[];
    const __half* A = g_scratch;
    const __half* B = g_Whf;

    int tid  = threadIdx.x;
    int warp = tid >> 5, lane = tid & 31;
    int wm = warp >> 2, wn = warp & 3;     // 2 x 4 warp grid
    int bm = blockIdx.y, bn = blockIdx.x;

    float c[4][4][4];
#pragma unroll
    for (int mi = 0; mi < 4; mi++)
#pragma unroll
        for (int ni = 0; ni < 4; ni++)
#pragma unroll
            for (int k = 0; k < 4; k++) c[mi][ni][k] = 0.f;

    uint32_t smb = (uint32_t)__cvta_generic_to_shared(sm);
    const __half* gA = A + (size_t)(bm * 128) * 512;
    const __half* gB = B + (size_t)(bn * 128) * 512;

    // Staging: per stage per operand 512 16B-chunks (4 per 64B row); each
    // thread does 2 chunks per operand.
    auto produce = [&](int kt, int s) {
        uint32_t st = smb + (uint32_t)s * (STAGE_WORDS * 4);
        int kc = kt * 32;
#pragma unroll
        for (int i = 0; i < 2; i++) {
            int u = i * 256 + tid;
            int row = u >> 2, cc = u & 3;
            cp_async16(st + (row * ROWW + cc * 4) * 4,
                       gA + (size_t)row * 512 + kc + cc * 8);
            cp_async16(st + ((128 + row) * ROWW + cc * 4) * 4,
                       gB + (size_t)row * 512 + kc + cc * 8);
        }
        CP_COMMIT();
    };

    produce(0, 0);
    produce(1, 1);
    produce(2, 2);

    // Per-lane ldmatrix base addresses (bytes from smem base).
    // A x4 for (mi,ks): matrices j: row = wm*64+mi*16 + (j&1)*8 + (l&7),
    //                   k-words = ks*8 + (j>>1)*4.
    // B x4 for (pair p,ks): matrices j: row = 128+wn*32+p*16 + (j>>1)*8+(l&7),
    //                   k-words = ks*8 + (j&1)*4.  regs: (b[2p],b[2p+1]) x2.
    int j = lane >> 3;
    uint32_t aAddr0 = smb
        + ((uint32_t)((wm * 64 + (j & 1) * 8 + (lane & 7)) * ROWW + (lane >> 4) * 4)) * 4;
    uint32_t bAddr0 = smb
        + ((uint32_t)((128 + wn * 32 + (j >> 1) * 8 + (lane & 7)) * ROWW + (j & 1) * 4)) * 4;

    for (int kt = 0; kt < 16; kt++) {
        int s = kt & 3;
        CP_WAIT(2);
        __syncthreads();
        if (kt + 3 < 16) produce(kt + 3, (kt + 3) & 3);

        uint32_t sOff = (uint32_t)s * (STAGE_WORDS * 4);
#pragma unroll
        for (int ks = 0; ks < 2; ks++) {
            uint32_t af[4][4], bf[4][2];
#pragma unroll
            for (int mi = 0; mi < 4; mi++)
                ldsm4(af[mi], aAddr0 + sOff + (uint32_t)(mi * 16 * ROWW + ks * 8) * 4);
#pragma unroll
            for (int p = 0; p < 2; p++) {
                uint32_t r[4];
                ldsm4(r, bAddr0 + sOff + (uint32_t)(p * 16 * ROWW + ks * 8) * 4);
                bf[2 * p][0] = r[0]; bf[2 * p][1] = r[1];
                bf[2 * p + 1][0] = r[2]; bf[2 * p + 1][1] = r[3];
            }
#pragma unroll
            for (int mi = 0; mi < 4; mi++)
#pragma unroll
                for (int ni = 0; ni < 4; ni++)
                    mma16(c[mi][ni], af[mi], bf[ni]);
        }
    }

    // Epilogue: C = acc + bias
    int g = lane >> 2, t = lane & 3;
#pragma unroll
    for (int mi = 0; mi < 4; mi++) {
        int row = bm * 128 + wm * 64 + mi * 16 + g;
#pragma unroll
        for (int ni = 0; ni < 4; ni++) {
            int col = bn * 128 + wn * 32 + ni * 8 + 2 * t;
            float2 bv = *(const float2*)&bias[col];
            *(float2*)&C[(size_t)row * 512 + col] =
                make_float2(c[mi][ni][0] + bv.x, c[mi][ni][1] + bv.y);
            *(float2*)&C[(size_t)(row + 8) * 512 + col] =
                make_float2(c[mi][ni][2] + bv.x, c[mi][ni][3] + bv.y);
        }
    }
}

// ---------------------------------------------------------------------------
extern "C" void kernel_launch(void* const* d_in, const int* in_sizes, int n_in,
                              void* d_out, int out_size)
{
    const float* x     = (const float*)d_in[0];
    const float* theta = (const float*)d_in[1];
    const float* Wm    = (const float*)d_in[2];
    const float* bias  = (const float*)d_in[3];
    float* out = (float*)d_out;

    cudaFuncSetAttribute(gemm_kernel,
                         cudaFuncAttributeMaxDynamicSharedMemorySize, GEMM_SMEM);

    attn_kernel<<<M_TOTAL / 4, 256>>>(x, theta, Wm);

    dim3 grid(4, 128);  // (N tiles, M tiles)
    gemm_kernel<<<grid, 256, GEMM_SMEM>>>(bias, out);
}

// round 8
// speedup vs baseline: 2.4856x; 1.5101x over previous
#include <cuda_runtime.h>
#include <cuda_fp16.h>
#include <cstdint>

#define EMBED 512
#define NB 8
#define NS 2048
#define M_TOTAL (NB * NS)   // 16384 rows

// attn output in (b, h, s, d) contiguous layout == the reference's buggy
// reshape. Stored as fp16 (10-bit mantissa == tf32) for the fp16 GEMM.
__device__ __half g_scratch[M_TOTAL * EMBED];  // 16 MB static device scratch
__device__ __half g_Whf[EMBED * EMBED];        // fp16-rounded W (0.5 MB)

// 1/sqrt(8) * log2(e)
#define SCALE_F (0.35355339059327373f * 1.4426950408889634f)

// ---------------------------------------------------------------------------
// helpers
// ---------------------------------------------------------------------------
__device__ __forceinline__ float ex2f(float a) {
    float r;
    asm("ex2.approx.ftz.f32 %0, %1;" : "=f"(r) : "f"(a));
    return r;
}
__device__ __forceinline__ uint32_t cvt_f16x2(float hi, float lo) {
    uint32_t r;
    asm("cvt.rn.f16x2.f32 %0, %1, %2;" : "=r"(r) : "f"(hi), "f"(lo));
    return r;
}
__device__ __forceinline__ uint32_t smem_u32(const void* p) {
    return (uint32_t)__cvta_generic_to_shared(p);
}

__device__ __forceinline__ void cp_async16(uint32_t dst, const void* src) {
    asm volatile("cp.async.cg.shared.global [%0], [%1], 16;" :: "r"(dst), "l"(src));
}
#define CP_COMMIT() asm volatile("cp.async.commit_group;")
#define CP_WAIT(n)  asm volatile("cp.async.wait_group %0;" :: "n"(n))

__device__ __forceinline__ void ldsm4(uint32_t* r, uint32_t addr) {
    asm volatile("ldmatrix.sync.aligned.m8n8.x4.shared.b16 {%0,%1,%2,%3}, [%4];"
                 : "=r"(r[0]), "=r"(r[1]), "=r"(r[2]), "=r"(r[3]) : "r"(addr));
}
__device__ __forceinline__ void ldsm4t(uint32_t* r, uint32_t addr) {
    asm volatile("ldmatrix.sync.aligned.m8n8.x4.trans.shared.b16 {%0,%1,%2,%3}, [%4];"
                 : "=r"(r[0]), "=r"(r[1]), "=r"(r[2]), "=r"(r[3]) : "r"(addr));
}

__device__ __forceinline__ void mma_k8(float* c, const uint32_t* a, uint32_t b) {
    asm volatile(
        "mma.sync.aligned.m16n8k8.row.col.f32.f16.f16.f32 "
        "{%0,%1,%2,%3}, {%4,%5}, {%6}, {%0,%1,%2,%3};\n"
        : "+f"(c[0]), "+f"(c[1]), "+f"(c[2]), "+f"(c[3])
        : "r"(a[0]), "r"(a[1]), "r"(b));
}
__device__ __forceinline__ void mma16(float* c, const uint32_t* a, const uint32_t* b) {
    asm volatile(
        "mma.sync.aligned.m16n8k16.row.col.f32.f16.f16.f32 "
        "{%0,%1,%2,%3}, {%4,%5,%6,%7}, {%8,%9}, {%0,%1,%2,%3};\n"
        : "+f"(c[0]), "+f"(c[1]), "+f"(c[2]), "+f"(c[3])
        : "r"(a[0]), "r"(a[1]), "r"(a[2]), "r"(a[3]), "r"(b[0]), "r"(b[1]));
}

// ---------------------------------------------------------------------------
// Kernel 1: warp-per-token tensor-core attention.
// P = cos(x + theta) (64 heads x 8 dims, fp16 in smem; Ps = SC*P).
// S = Ps * P^T via mma.m16n8k8 (B = P non-trans: P is n-major for mma1).
// p = exp2(S) on f32 D fragments; the m16n8 D layout == m16n8k16 A layout,
// so cvt.f16x2 pairs feed mma2 directly. Row sums via 2 butterfly shuffles.
// out = S~ * P via mma.m16n8k16 (B = P trans-loaded: k-major for mma2).
// Blocks 0..255 additionally round W to fp16.
// ---------------------------------------------------------------------------
__global__ __launch_bounds__(256) void attn_kernel(
    const float* __restrict__ x, const float* __restrict__ theta,
    const float* __restrict__ W)
{
    __shared__ __align__(16) __half Pb[8 * 512];   // per-warp P   (64x8)
    __shared__ __align__(16) __half Psb[8 * 512];  // per-warp SC*P
    __shared__ float th[8];
    int tid = threadIdx.x;

    // Fold W fp16-rounding into the first 256 blocks (65536 float4s total).
    if (blockIdx.x < 256) {
        int i = blockIdx.x * 256 + tid;
        float4 v = ((const float4*)W)[i];
        __half2 h0 = __floats2half2_rn(v.x, v.y);
        __half2 h1 = __floats2half2_rn(v.z, v.w);
        uint2 u;
        u.x = *(uint32_t*)&h0;
        u.y = *(uint32_t*)&h1;
        ((uint2*)g_Whf)[i] = u;
    }

    if (tid < 8) th[tid] = theta[tid];
    __syncthreads();

    int w = tid >> 5, lane = tid & 31;
    int token = blockIdx.x * 8 + w;
    const float* xt = x + (size_t)token * 512;
    __half* P  = Pb  + w * 512;
    __half* Ps = Psb + w * 512;

    // proj: lane handles head rows (lane) and (lane+32); 8 dims each.
#pragma unroll
    for (int rr = 0; rr < 2; rr++) {
        int row = lane + rr * 32;
        float4 v0 = *(const float4*)(xt + row * 8);
        float4 v1 = *(const float4*)(xt + row * 8 + 4);
        float c0 = __cosf(v0.x + th[0]);
        float c1 = __cosf(v0.y + th[1]);
        float c2 = __cosf(v0.z + th[2]);
        float c3 = __cosf(v0.w + th[3]);
        float c4 = __cosf(v1.x + th[4]);
        float c5 = __cosf(v1.y + th[5]);
        float c6 = __cosf(v1.z + th[6]);
        float c7 = __cosf(v1.w + th[7]);
        uint4 up, us;
        up.x = cvt_f16x2(c1, c0); up.y = cvt_f16x2(c3, c2);
        up.z = cvt_f16x2(c5, c4); up.w = cvt_f16x2(c7, c6);
        us.x = cvt_f16x2(c1 * SCALE_F, c0 * SCALE_F);
        us.y = cvt_f16x2(c3 * SCALE_F, c2 * SCALE_F);
        us.z = cvt_f16x2(c5 * SCALE_F, c4 * SCALE_F);
        us.w = cvt_f16x2(c7 * SCALE_F, c6 * SCALE_F);
        *(uint4*)(P + row * 8)  = up;
        *(uint4*)(Ps + row * 8) = us;
    }
    __syncwarp();

    // Fragment loads (all loop-invariant for the token).
    uint32_t pA0 = smem_u32(Ps + lane * 8);
    uint32_t pA1 = smem_u32(Ps + (lane + 32) * 8);
    uint32_t pB0 = smem_u32(P + lane * 8);
    uint32_t pB1 = smem_u32(P + (lane + 32) * 8);
    uint32_t a[8], b1[8], bt[8];
    ldsm4(a, pA0);      ldsm4(a + 4, pA1);      // A of mma1 (rows = heads h)
    ldsm4(b1, pB0);     ldsm4(b1 + 4, pB1);     // B of mma1 (P n-major)
    ldsm4t(bt, pB0);    ldsm4t(bt + 4, pB1);    // B of mma2 (P^T, k-major)

    int b = token >> 11;
    int s = token & 2047;
    int g = lane >> 2, t = lane & 3;
    size_t obase = ((size_t)b << 20) + ((size_t)s << 3) + 2 * t;

#pragma unroll
    for (int mi = 0; mi < 4; mi++) {
        // S rows [16mi, 16mi+16): 8 mmas over ni (already SC-scaled via Ps).
        float D[8][4];
#pragma unroll
        for (int ni = 0; ni < 8; ni++) {
            D[ni][0] = 0.f; D[ni][1] = 0.f; D[ni][2] = 0.f; D[ni][3] = 0.f;
            mma_k8(D[ni], &a[2 * mi], b1[ni]);
        }
        // exp2 + row sums + fp16 pack (D fragment == mma2 A fragment layout).
        float lg = 0.f, lg8 = 0.f;
        uint32_t slo[8], shi[8];
#pragma unroll
        for (int ni = 0; ni < 8; ni++) {
            float e0 = ex2f(D[ni][0]);
            float e1 = ex2f(D[ni][1]);
            float e2 = ex2f(D[ni][2]);
            float e3 = ex2f(D[ni][3]);
            lg  += e0 + e1;
            lg8 += e2 + e3;
            slo[ni] = cvt_f16x2(e1, e0);   // row g,   cols 2t,2t+1
            shi[ni] = cvt_f16x2(e3, e2);   // row g+8
        }
        lg  += __shfl_xor_sync(0xffffffffu, lg, 1);
        lg  += __shfl_xor_sync(0xffffffffu, lg, 2);
        lg8 += __shfl_xor_sync(0xffffffffu, lg8, 1);
        lg8 += __shfl_xor_sync(0xffffffffu, lg8, 2);

        // out rows = S~ * P : 4 mmas m16n8k16 over g-blocks.
        float o[4] = {0.f, 0.f, 0.f, 0.f};
#pragma unroll
        for (int kb = 0; kb < 4; kb++) {
            uint32_t af[4] = { slo[2 * kb], shi[2 * kb],
                               slo[2 * kb + 1], shi[2 * kb + 1] };
            mma16(o, af, &bt[2 * kb]);
        }
        float ig = 1.0f / lg, ig8 = 1.0f / lg8;

        int h0 = 16 * mi + g;
        uint32_t r0 = cvt_f16x2(o[1] * ig, o[0] * ig);
        uint32_t r1 = cvt_f16x2(o[3] * ig8, o[2] * ig8);
        *(uint32_t*)(g_scratch + obase + ((size_t)h0 << 14)) = r0;
        *(uint32_t*)(g_scratch + obase + ((size_t)(h0 + 8) << 14)) = r1;
    }
}

// ---------------------------------------------------------------------------
// Kernel 2: C[16384,512] = scratch @ W^T + bias, fp16 mma m16n8k16 (f32 acc).
// Block tile 128x128, BK=32, 8 warps (2x4), warp tile 64x32.
// 5-stage cp.async pipeline (20KB/stage, dynamic smem, 2 CTA/SM).
// fp16 rows padded to 20 words: ldmatrix phases conflict-free.
// ---------------------------------------------------------------------------
#define ROWW 20                    // words per padded 16-word (32-half) row
#define STAGE_WORDS (256 * ROWW)   // A(128 rows) + B(128 rows) = 5120 words
#define NSTAGE 5
#define GEMM_SMEM (NSTAGE * STAGE_WORDS * 4)   // 102400 bytes

__global__ __launch_bounds__(256) void gemm_kernel(
    const float* __restrict__ bias,   // [512]
    float* __restrict__ C)            // [16384][512]
{
    extern __shared__ __align__(16) uint32_t sm[];
    const __half* A = g_scratch;
    const __half* B = g_Whf;

    int tid  = threadIdx.x;
    int warp = tid >> 5, lane = tid & 31;
    int wm = warp >> 2, wn = warp & 3;     // 2 x 4 warp grid
    int bm = blockIdx.y, bn = blockIdx.x;

    float c[4][4][4];
#pragma unroll
    for (int mi = 0; mi < 4; mi++)
#pragma unroll
        for (int ni = 0; ni < 4; ni++)
#pragma unroll
            for (int k = 0; k < 4; k++) c[mi][ni][k] = 0.f;

    uint32_t smb = (uint32_t)__cvta_generic_to_shared(sm);
    const __half* gA = A + (size_t)(bm * 128) * 512;
    const __half* gB = B + (size_t)(bn * 128) * 512;

    auto produce = [&](int kt, int s) {
        uint32_t st = smb + (uint32_t)s * (STAGE_WORDS * 4);
        int kc = kt * 32;
#pragma unroll
        for (int i = 0; i < 2; i++) {
            int u = i * 256 + tid;
            int row = u >> 2, cc = u & 3;
            cp_async16(st + (row * ROWW + cc * 4) * 4,
                       gA + (size_t)row * 512 + kc + cc * 8);
            cp_async16(st + ((128 + row) * ROWW + cc * 4) * 4,
                       gB + (size_t)row * 512 + kc + cc * 8);
        }
        CP_COMMIT();
    };

    produce(0, 0);
    produce(1, 1);
    produce(2, 2);
    produce(3, 3);

    int j = lane >> 3;
    uint32_t aAddr0 = smb
        + ((uint32_t)((wm * 64 + (j & 1) * 8 + (lane & 7)) * ROWW + (lane >> 4) * 4)) * 4;
    uint32_t bAddr0 = smb
        + ((uint32_t)((128 + wn * 32 + (j >> 1) * 8 + (lane & 7)) * ROWW + (j & 1) * 4)) * 4;

    for (int kt = 0; kt < 16; kt++) {
        int s = kt % NSTAGE;
        CP_WAIT(3);
        __syncthreads();
        if (kt + 4 < 16) produce(kt + 4, (kt + 4) % NSTAGE);

        uint32_t sOff = (uint32_t)s * (STAGE_WORDS * 4);
#pragma unroll
        for (int ks = 0; ks < 2; ks++) {
            uint32_t af[4][4], bf[4][2];
#pragma unroll
            for (int mi = 0; mi < 4; mi++)
                ldsm4(af[mi], aAddr0 + sOff + (uint32_t)(mi * 16 * ROWW + ks * 8) * 4);
#pragma unroll
            for (int p = 0; p < 2; p++) {
                uint32_t r[4];
                ldsm4(r, bAddr0 + sOff + (uint32_t)(p * 16 * ROWW + ks * 8) * 4);
                bf[2 * p][0] = r[0]; bf[2 * p][1] = r[1];
                bf[2 * p + 1][0] = r[2]; bf[2 * p + 1][1] = r[3];
            }
#pragma unroll
            for (int mi = 0; mi < 4; mi++)
#pragma unroll
                for (int ni = 0; ni < 4; ni++)
                    mma16(c[mi][ni], af[mi], bf[ni]);
        }
    }

    // Epilogue: C = acc + bias
    int g = lane >> 2, t = lane & 3;
#pragma unroll
    for (int mi = 0; mi < 4; mi++) {
        int row = bm * 128 + wm * 64 + mi * 16 + g;
#pragma unroll
        for (int ni = 0; ni < 4; ni++) {
            int col = bn * 128 + wn * 32 + ni * 8 + 2 * t;
            float2 bv = *(const float2*)&bias[col];
            *(float2*)&C[(size_t)row * 512 + col] =
                make_float2(c[mi][ni][0] + bv.x, c[mi][ni][1] + bv.y);
            *(float2*)&C[(size_t)(row + 8) * 512 + col] =
                make_float2(c[mi][ni][2] + bv.x, c[mi][ni][3] + bv.y);
        }
    }
}

// ---------------------------------------------------------------------------
extern "C" void kernel_launch(void* const* d_in, const int* in_sizes, int n_in,
                              void* d_out, int out_size)
{
    const float* x     = (const float*)d_in[0];
    const float* theta = (const float*)d_in[1];
    const float* Wm    = (const float*)d_in[2];
    const float* bias  = (const float*)d_in[3];
    float* out = (float*)d_out;

    cudaFuncSetAttribute(gemm_kernel,
                         cudaFuncAttributeMaxDynamicSharedMemorySize, GEMM_SMEM);

    attn_kernel<<<M_TOTAL / 8, 256>>>(x, theta, Wm);

    dim3 grid(4, 128);  // (N tiles, M tiles)
    gemm_kernel<<<grid, 256, GEMM_SMEM>>>(bias, out);
}

// round 9
// speedup vs baseline: 2.6949x; 1.0842x over previous
#include <cuda_runtime.h>
#include <cuda_fp16.h>
#include <cstdint>

#define EMBED 512
#define NB 8
#define NS 2048
#define M_TOTAL (NB * NS)   // 16384 rows

// attn output in (b, h, s, d) contiguous layout == the reference's buggy
// reshape. Stored as fp16 (10-bit mantissa == tf32) for the fp16 GEMM.
__device__ __half g_scratch[M_TOTAL * EMBED];  // 16 MB static device scratch
__device__ __half g_Whf[EMBED * EMBED];        // fp16-rounded W (0.5 MB)

// 1/sqrt(8) * log2(e)
#define SCALE_F (0.35355339059327373f * 1.4426950408889634f)

// ---------------------------------------------------------------------------
// helpers
// ---------------------------------------------------------------------------
__device__ __forceinline__ float ex2f(float a) {
    float r;
    asm("ex2.approx.ftz.f32 %0, %1;" : "=f"(r) : "f"(a));
    return r;
}
__device__ __forceinline__ uint32_t cvt_f16x2(float hi, float lo) {
    uint32_t r;
    asm("cvt.rn.f16x2.f32 %0, %1, %2;" : "=r"(r) : "f"(hi), "f"(lo));
    return r;
}
__device__ __forceinline__ uint32_t smem_u32(const void* p) {
    return (uint32_t)__cvta_generic_to_shared(p);
}

__device__ __forceinline__ void cp_async16(uint32_t dst, const void* src) {
    asm volatile("cp.async.cg.shared.global [%0], [%1], 16;" :: "r"(dst), "l"(src));
}
#define CP_COMMIT() asm volatile("cp.async.commit_group;")
#define CP_WAIT(n)  asm volatile("cp.async.wait_group %0;" :: "n"(n))

__device__ __forceinline__ void ldsm4(uint32_t* r, uint32_t addr) {
    asm volatile("ldmatrix.sync.aligned.m8n8.x4.shared.b16 {%0,%1,%2,%3}, [%4];"
                 : "=r"(r[0]), "=r"(r[1]), "=r"(r[2]), "=r"(r[3]) : "r"(addr));
}
__device__ __forceinline__ void ldsm4t(uint32_t* r, uint32_t addr) {
    asm volatile("ldmatrix.sync.aligned.m8n8.x4.trans.shared.b16 {%0,%1,%2,%3}, [%4];"
                 : "=r"(r[0]), "=r"(r[1]), "=r"(r[2]), "=r"(r[3]) : "r"(addr));
}

__device__ __forceinline__ void mma_k8(float* c, const uint32_t* a, uint32_t b) {
    asm volatile(
        "mma.sync.aligned.m16n8k8.row.col.f32.f16.f16.f32 "
        "{%0,%1,%2,%3}, {%4,%5}, {%6}, {%0,%1,%2,%3};\n"
        : "+f"(c[0]), "+f"(c[1]), "+f"(c[2]), "+f"(c[3])
        : "r"(a[0]), "r"(a[1]), "r"(b));
}
__device__ __forceinline__ void mma16(float* c, const uint32_t* a, const uint32_t* b) {
    asm volatile(
        "mma.sync.aligned.m16n8k16.row.col.f32.f16.f16.f32 "
        "{%0,%1,%2,%3}, {%4,%5,%6,%7}, {%8,%9}, {%0,%1,%2,%3};\n"
        : "+f"(c[0]), "+f"(c[1]), "+f"(c[2]), "+f"(c[3])
        : "r"(a[0]), "r"(a[1]), "r"(a[2]), "r"(a[3]), "r"(b[0]), "r"(b[1]));
}

// ---------------------------------------------------------------------------
// Kernel 1: warp-per-token tensor-core attention (unchanged from R8).
// ---------------------------------------------------------------------------
__global__ __launch_bounds__(256) void attn_kernel(
    const float* __restrict__ x, const float* __restrict__ theta,
    const float* __restrict__ W)
{
    __shared__ __align__(16) __half Pb[8 * 512];   // per-warp P   (64x8)
    __shared__ __align__(16) __half Psb[8 * 512];  // per-warp SC*P
    __shared__ float th[8];
    int tid = threadIdx.x;

    // Fold W fp16-rounding into the first 256 blocks (65536 float4s total).
    if (blockIdx.x < 256) {
        int i = blockIdx.x * 256 + tid;
        float4 v = ((const float4*)W)[i];
        __half2 h0 = __floats2half2_rn(v.x, v.y);
        __half2 h1 = __floats2half2_rn(v.z, v.w);
        uint2 u;
        u.x = *(uint32_t*)&h0;
        u.y = *(uint32_t*)&h1;
        ((uint2*)g_Whf)[i] = u;
    }

    if (tid < 8) th[tid] = theta[tid];
    __syncthreads();

    int w = tid >> 5, lane = tid & 31;
    int token = blockIdx.x * 8 + w;
    const float* xt = x + (size_t)token * 512;
    __half* P  = Pb  + w * 512;
    __half* Ps = Psb + w * 512;

#pragma unroll
    for (int rr = 0; rr < 2; rr++) {
        int row = lane + rr * 32;
        float4 v0 = *(const float4*)(xt + row * 8);
        float4 v1 = *(const float4*)(xt + row * 8 + 4);
        float c0 = __cosf(v0.x + th[0]);
        float c1 = __cosf(v0.y + th[1]);
        float c2 = __cosf(v0.z + th[2]);
        float c3 = __cosf(v0.w + th[3]);
        float c4 = __cosf(v1.x + th[4]);
        float c5 = __cosf(v1.y + th[5]);
        float c6 = __cosf(v1.z + th[6]);
        float c7 = __cosf(v1.w + th[7]);
        uint4 up, us;
        up.x = cvt_f16x2(c1, c0); up.y = cvt_f16x2(c3, c2);
        up.z = cvt_f16x2(c5, c4); up.w = cvt_f16x2(c7, c6);
        us.x = cvt_f16x2(c1 * SCALE_F, c0 * SCALE_F);
        us.y = cvt_f16x2(c3 * SCALE_F, c2 * SCALE_F);
        us.z = cvt_f16x2(c5 * SCALE_F, c4 * SCALE_F);
        us.w = cvt_f16x2(c7 * SCALE_F, c6 * SCALE_F);
        *(uint4*)(P + row * 8)  = up;
        *(uint4*)(Ps + row * 8) = us;
    }
    __syncwarp();

    uint32_t pA0 = smem_u32(Ps + lane * 8);
    uint32_t pA1 = smem_u32(Ps + (lane + 32) * 8);
    uint32_t pB0 = smem_u32(P + lane * 8);
    uint32_t pB1 = smem_u32(P + (lane + 32) * 8);
    uint32_t a[8], b1[8], bt[8];
    ldsm4(a, pA0);      ldsm4(a + 4, pA1);
    ldsm4(b1, pB0);     ldsm4(b1 + 4, pB1);
    ldsm4t(bt, pB0);    ldsm4t(bt + 4, pB1);

    int b = token >> 11;
    int s = token & 2047;
    int g = lane >> 2, t = lane & 3;
    size_t obase = ((size_t)b << 20) + ((size_t)s << 3) + 2 * t;

#pragma unroll
    for (int mi = 0; mi < 4; mi++) {
        float D[8][4];
#pragma unroll
        for (int ni = 0; ni < 8; ni++) {
            D[ni][0] = 0.f; D[ni][1] = 0.f; D[ni][2] = 0.f; D[ni][3] = 0.f;
            mma_k8(D[ni], &a[2 * mi], b1[ni]);
        }
        float lg = 0.f, lg8 = 0.f;
        uint32_t slo[8], shi[8];
#pragma unroll
        for (int ni = 0; ni < 8; ni++) {
            float e0 = ex2f(D[ni][0]);
            float e1 = ex2f(D[ni][1]);
            float e2 = ex2f(D[ni][2]);
            float e3 = ex2f(D[ni][3]);
            lg  += e0 + e1;
            lg8 += e2 + e3;
            slo[ni] = cvt_f16x2(e1, e0);
            shi[ni] = cvt_f16x2(e3, e2);
        }
        lg  += __shfl_xor_sync(0xffffffffu, lg, 1);
        lg  += __shfl_xor_sync(0xffffffffu, lg, 2);
        lg8 += __shfl_xor_sync(0xffffffffu, lg8, 1);
        lg8 += __shfl_xor_sync(0xffffffffu, lg8, 2);

        float o[4] = {0.f, 0.f, 0.f, 0.f};
#pragma unroll
        for (int kb = 0; kb < 4; kb++) {
            uint32_t af[4] = { slo[2 * kb], shi[2 * kb],
                               slo[2 * kb + 1], shi[2 * kb + 1] };
            mma16(o, af, &bt[2 * kb]);
        }
        float ig = 1.0f / lg, ig8 = 1.0f / lg8;

        int h0 = 16 * mi + g;
        uint32_t r0 = cvt_f16x2(o[1] * ig, o[0] * ig);
        uint32_t r1 = cvt_f16x2(o[3] * ig8, o[2] * ig8);
        *(uint32_t*)(g_scratch + obase + ((size_t)h0 << 14)) = r0;
        *(uint32_t*)(g_scratch + obase + ((size_t)(h0 + 8) << 14)) = r1;
    }
}

// ---------------------------------------------------------------------------
// Kernel 2: C[16384,512] = scratch @ W^T + bias, fp16 mma m16n8k16 (f32 acc).
// Block tile 128x128, 4 warps (2x2), warp tile 64x64 (128 acc regs, fat ILP).
// 3-stage cp.async pipeline (20KB/stage) -> 3 CTAs/SM (180KB smem,
// __launch_bounds__(128,3) caps regs at 170). 16 LDSM : 64 HMMA per kt.
// fp16 rows padded to 20 words: ldmatrix phases conflict-free.
// ---------------------------------------------------------------------------
#define ROWW 20                    // words per padded 16-word (32-half) row
#define STAGE_WORDS (256 * ROWW)   // A(128 rows) + B(128 rows) = 5120 words
#define NSTAGE 3
#define GEMM_SMEM (NSTAGE * STAGE_WORDS * 4)   // 61440 bytes

__global__ void __launch_bounds__(128, 3) gemm_kernel(
    const float* __restrict__ bias,   // [512]
    float* __restrict__ C)            // [16384][512]
{
    extern __shared__ __align__(16) uint32_t sm[];
    const __half* A = g_scratch;
    const __half* B = g_Whf;

    int tid  = threadIdx.x;
    int warp = tid >> 5, lane = tid & 31;
    int wm = warp >> 1, wn = warp & 1;     // 2 x 2 warp grid, warp tile 64x64
    int bm = blockIdx.y, bn = blockIdx.x;

    float c[4][8][4];                      // [mi][ni][frag]: 128 regs
#pragma unroll
    for (int mi = 0; mi < 4; mi++)
#pragma unroll
        for (int ni = 0; ni < 8; ni++)
#pragma unroll
            for (int k = 0; k < 4; k++) c[mi][ni][k] = 0.f;

    uint32_t smb = (uint32_t)__cvta_generic_to_shared(sm);
    const __half* gA = A + (size_t)(bm * 128) * 512;
    const __half* gB = B + (size_t)(bn * 128) * 512;

    // Staging: 1024 16B-chunks per stage (A 512 + B 512), 8 per thread.
    auto produce = [&](int kt, int s) {
        uint32_t st = smb + (uint32_t)s * (STAGE_WORDS * 4);
        int kc = kt * 32;
#pragma unroll
        for (int i = 0; i < 4; i++) {
            int u = i * 128 + tid;
            int row = u >> 2, cc = u & 3;
            cp_async16(st + (row * ROWW + cc * 4) * 4,
                       gA + (size_t)row * 512 + kc + cc * 8);
            cp_async16(st + ((128 + row) * ROWW + cc * 4) * 4,
                       gB + (size_t)row * 512 + kc + cc * 8);
        }
        CP_COMMIT();
    };

    produce(0, 0);
    produce(1, 1);

    // ldmatrix bases. A x4 for (mi,ks): row = wm*64+mi*16+(j&1)*8+(lane&7),
    // kword = ks*8 + (lane>>4)*4.  B x4 for (p,ks): row = 128+wn*64+p*16+
    // (j>>1)*8+(lane&7), kword = ks*8 + (j&1)*4; gives n-chunks 2p, 2p+1.
    int j = lane >> 3;
    uint32_t aAddr0 = smb
        + ((uint32_t)((wm * 64 + (j & 1) * 8 + (lane & 7)) * ROWW + (lane >> 4) * 4)) * 4;
    uint32_t bAddr0 = smb
        + ((uint32_t)((128 + wn * 64 + (j >> 1) * 8 + (lane & 7)) * ROWW + (j & 1) * 4)) * 4;

    for (int kt = 0; kt < 16; kt++) {
        int s = kt % 3;
        CP_WAIT(1);
        __syncthreads();
        if (kt + 2 < 16) produce(kt + 2, (kt + 2) % 3);

        uint32_t sOff = (uint32_t)s * (STAGE_WORDS * 4);
#pragma unroll
        for (int ks = 0; ks < 2; ks++) {
            uint32_t af[4][4];
#pragma unroll
            for (int mi = 0; mi < 4; mi++)
                ldsm4(af[mi], aAddr0 + sOff + (uint32_t)(mi * 16 * ROWW + ks * 8) * 4);
#pragma unroll
            for (int p = 0; p < 4; p++) {
                uint32_t r[4];
                ldsm4(r, bAddr0 + sOff + (uint32_t)(p * 16 * ROWW + ks * 8) * 4);
#pragma unroll
                for (int mi = 0; mi < 4; mi++) {
                    mma16(c[mi][2 * p],     af[mi], r);
                    mma16(c[mi][2 * p + 1], af[mi], r + 2);
                }
            }
        }
    }

    // Epilogue: C = acc + bias
    int g = lane >> 2, t = lane & 3;
#pragma unroll
    for (int mi = 0; mi < 4; mi++) {
        int row = bm * 128 + wm * 64 + mi * 16 + g;
#pragma unroll
        for (int ni = 0; ni < 8; ni++) {
            int col = bn * 128 + wn * 64 + ni * 8 + 2 * t;
            float2 bv = *(const float2*)&bias[col];
            *(float2*)&C[(size_t)row * 512 + col] =
                make_float2(c[mi][ni][0] + bv.x, c[mi][ni][1] + bv.y);
            *(float2*)&C[(size_t)(row + 8) * 512 + col] =
                make_float2(c[mi][ni][2] + bv.x, c[mi][ni][3] + bv.y);
        }
    }
}

// ---------------------------------------------------------------------------
extern "C" void kernel_launch(void* const* d_in, const int* in_sizes, int n_in,
                              void* d_out, int out_size)
{
    const float* x     = (const float*)d_in[0];
    const float* theta = (const float*)d_in[1];
    const float* Wm    = (const float*)d_in[2];
    const float* bias  = (const float*)d_in[3];
    float* out = (float*)d_out;

    cudaFuncSetAttribute(gemm_kernel,
                         cudaFuncAttributeMaxDynamicSharedMemorySize, GEMM_SMEM);

    attn_kernel<<<M_TOTAL / 8, 256>>>(x, theta, Wm);

    dim3 grid(4, 128);  // (N tiles, M tiles)
    gemm_kernel<<<grid, 128, GEMM_SMEM>>>(bias, out);
}